// round 3
// baseline (speedup 1.0000x reference)
#include <cuda_runtime.h>
#include <cstdint>

// ---------------------------------------------------------------------------
// VQ quantization, bit-faithful argmin emulation:
//   dot   : strictly sequential fp32 FMA over ascending k (per output elem)
//   dist  : RN(RN(z2 - 2*dot) + e2)   (reference association)
//   argmin: lowest-index tie break (packed u64 key)
//   z_st  : RN(z + RN(z_q - z))
// ---------------------------------------------------------------------------

#define TOKENS      32768
#define HID         256
#define NCODES      8192
#define M_TILE      128
#define N_TILE      128
#define KC          32
#define NBLOCKS     (TOKENS / M_TILE)     // 256
#define NTILES      (NCODES / N_TILE)     // 64
#define Z_ST_ELEMS  (TOKENS * HID)
#define FULL_OUT    (Z_ST_ELEMS + TOKENS + 2)

typedef unsigned long long ull;

__device__ float  g_e2[NCODES];
__device__ double g_part[NBLOCKS];

// shared memory: As[256][128] f32 (128KB) + Bs[32][128] f32 (16KB) + extras
#define AS_FLOATS (HID * M_TILE)
#define BS_FLOATS (KC * N_TILE)
#define SMEM_BYTES (AS_FLOATS*4 + BS_FLOATS*4 + 128*8 + 128*4 + 8)

__device__ __forceinline__ void ffma2(ull& d, ull a, ull b) {
    asm("fma.rn.f32x2 %0, %1, %2, %0;" : "+l"(d) : "l"(a), "l"(b));
}
__device__ __forceinline__ ull dup2(float s) {
    ull d;
    asm("mov.b64 %0, {%1, %1};" : "=l"(d) : "f"(s));
    return d;
}
__device__ __forceinline__ unsigned fkey(float f) {
    unsigned u = __float_as_uint(f);
    return (u & 0x80000000u) ? ~u : (u | 0x80000000u);
}

// --- ||e||^2 per code, correctly rounded via double ------------------------
__global__ void e2_kernel(const float* __restrict__ emb) {
    int code = blockIdx.x * 8 + (threadIdx.x >> 5);
    int lane = threadIdx.x & 31;
    const float4* r = (const float4*)(emb + (size_t)code * HID);
    double s = 0.0;
    #pragma unroll
    for (int j = lane; j < HID / 4; j += 32) {
        float4 v = r[j];
        s += (double)v.x * v.x + (double)v.y * v.y +
             (double)v.z * v.z + (double)v.w * v.w;
    }
    #pragma unroll
    for (int o = 16; o; o >>= 1)
        s += __shfl_down_sync(0xffffffffu, s, o);
    if (lane == 0) g_e2[code] = (float)s;
}

// --- main kernel ------------------------------------------------------------
__global__ void __launch_bounds__(256, 1)
vq_main(const float* __restrict__ z, const float* __restrict__ emb,
        float* __restrict__ out_zst, float* __restrict__ out_idx,
        int write_extra) {
    extern __shared__ char smem[];
    float* As = (float*)smem;                        // [HID][M_TILE]
    float* Bs = As + AS_FLOATS;                      // [KC][N_TILE]
    ull*    minkey = (ull*)(Bs + BS_FLOATS);         // [128]
    float*  z2s = (float*)(minkey + 128);            // [128]
    double* bsum = (double*)(z2s + 128);

    const int tid = threadIdx.x;
    const int tx = tid & 15;         // n: owns n = tx*8 .. tx*8+7
    const int ty = tid >> 4;         // m: owns m = ty*8 .. ty*8+7
    const int tokBase = blockIdx.x * M_TILE;

    // ---- load A tile (z, full K) into smem, k-major: As[k][m] ----
    {
        const float4* zg4 = (const float4*)(z + (size_t)tokBase * HID);
        #pragma unroll 4
        for (int i = tid; i < M_TILE * (HID / 4); i += 256) {
            int m  = i & 127;
            int kq = i >> 7;           // 0..63
            float4 v = zg4[(size_t)m * (HID / 4) + kq];
            As[(kq * 4 + 0) * M_TILE + m] = v.x;
            As[(kq * 4 + 1) * M_TILE + m] = v.y;
            As[(kq * 4 + 2) * M_TILE + m] = v.z;
            As[(kq * 4 + 3) * M_TILE + m] = v.w;
        }
    }
    __syncthreads();

    // ---- z2 per token (correctly rounded), init minkey ----
    if (tid < 128) {
        double s = 0.0;
        for (int k = 0; k < HID; ++k) {
            float v = As[k * M_TILE + tid];
            s += (double)v * v;
        }
        z2s[tid] = (float)s;
        minkey[tid] = ~0ull;
    }
    if (tid == 0) *bsum = 0.0;
    __syncthreads();

    // B prefetch lane mapping: thread loads code n=ldn, k-quads ldkq+2j
    const int ldn  = tid & 127;
    const int ldkq = tid >> 7;       // 0 or 1
    const float4* eg4 = (const float4*)emb;  // emb[n][k]: idx n*64 + k/4

    for (int nt = 0; nt < NTILES; ++nt) {
        const int nBase = nt * N_TILE;

        ull acc[32];                 // acc[mi*8+nj]: lanes = (m=ty*8+2mi, m+1)
        #pragma unroll
        for (int i = 0; i < 32; ++i) acc[i] = 0ull;

        // prefetch chunk kc=0 of this n-tile
        float4 pf[4];
        #pragma unroll
        for (int j = 0; j < 4; ++j)
            pf[j] = eg4[(size_t)(nBase + ldn) * (HID / 4) + (ldkq + 2 * j)];

        for (int kc = 0; kc < HID / KC; ++kc) {
            __syncthreads();         // Bs consumers of previous chunk done
            // store prefetched chunk: Bs[kk][n]
            #pragma unroll
            for (int j = 0; j < 4; ++j) {
                int kk = (ldkq + 2 * j) * 4;   // local k within chunk
                Bs[(kk + 0) * N_TILE + ldn] = pf[j].x;
                Bs[(kk + 1) * N_TILE + ldn] = pf[j].y;
                Bs[(kk + 2) * N_TILE + ldn] = pf[j].z;
                Bs[(kk + 3) * N_TILE + ldn] = pf[j].w;
            }
            // prefetch next chunk (overlaps FMA section)
            if (kc + 1 < HID / KC) {
                int kqBase = (kc + 1) * (KC / 4);
                #pragma unroll
                for (int j = 0; j < 4; ++j)
                    pf[j] = eg4[(size_t)(nBase + ldn) * (HID / 4) +
                                kqBase + (ldkq + 2 * j)];
            }
            __syncthreads();

            const int kBase = kc * KC;
            #pragma unroll 2
            for (int kk = 0; kk < KC; ++kk) {
                const int k = kBase + kk;
                const ull* a8 = (const ull*)(As + k * M_TILE) + ty * 4;
                ull a0 = a8[0], a1 = a8[1], a2 = a8[2], a3 = a8[3];
                const float4* b4 = (const float4*)(Bs + kk * N_TILE) + tx * 2;
                float4 bA = b4[0], bB = b4[1];
                ull bb0 = dup2(bA.x), bb1 = dup2(bA.y),
                    bb2 = dup2(bA.z), bb3 = dup2(bA.w);
                ull bb4 = dup2(bB.x), bb5 = dup2(bB.y),
                    bb6 = dup2(bB.z), bb7 = dup2(bB.w);
                ffma2(acc[ 0], a0, bb0); ffma2(acc[ 1], a0, bb1);
                ffma2(acc[ 2], a0, bb2); ffma2(acc[ 3], a0, bb3);
                ffma2(acc[ 4], a0, bb4); ffma2(acc[ 5], a0, bb5);
                ffma2(acc[ 6], a0, bb6); ffma2(acc[ 7], a0, bb7);
                ffma2(acc[ 8], a1, bb0); ffma2(acc[ 9], a1, bb1);
                ffma2(acc[10], a1, bb2); ffma2(acc[11], a1, bb3);
                ffma2(acc[12], a1, bb4); ffma2(acc[13], a1, bb5);
                ffma2(acc[14], a1, bb6); ffma2(acc[15], a1, bb7);
                ffma2(acc[16], a2, bb0); ffma2(acc[17], a2, bb1);
                ffma2(acc[18], a2, bb2); ffma2(acc[19], a2, bb3);
                ffma2(acc[20], a2, bb4); ffma2(acc[21], a2, bb5);
                ffma2(acc[22], a2, bb6); ffma2(acc[23], a2, bb7);
                ffma2(acc[24], a3, bb0); ffma2(acc[25], a3, bb1);
                ffma2(acc[26], a3, bb2); ffma2(acc[27], a3, bb3);
                ffma2(acc[28], a3, bb4); ffma2(acc[29], a3, bb5);
                ffma2(acc[30], a3, bb6); ffma2(acc[31], a3, bb7);
            }
        }

        // ---- epilogue: dist + packed argmin (reference rounding chain) ----
        #pragma unroll
        for (int mi = 0; mi < 4; ++mi) {
            int m0 = ty * 8 + 2 * mi;
            float zz0 = z2s[m0], zz1 = z2s[m0 + 1];
            ull best0 = ~0ull, best1 = ~0ull;
            #pragma unroll
            for (int nj = 0; nj < 8; ++nj) {
                int n = nBase + tx * 8 + nj;
                float e2 = __ldg(&g_e2[n]);
                ull A = acc[mi * 8 + nj];
                float dlo = __uint_as_float((unsigned)(A & 0xffffffffull));
                float dhi = __uint_as_float((unsigned)(A >> 32));
                float dist0 = (zz0 - 2.0f * dlo) + e2;
                float dist1 = (zz1 - 2.0f * dhi) + e2;
                ull k0 = ((ull)fkey(dist0) << 32) | (unsigned)n;
                ull k1 = ((ull)fkey(dist1) << 32) | (unsigned)n;
                if (k0 < best0) best0 = k0;
                if (k1 < best1) best1 = k1;
            }
            atomicMin(&minkey[m0], best0);
            atomicMin(&minkey[m0 + 1], best1);
        }
    }
    __syncthreads();

    // ---- phase 2: z_st = z + (z_q - z), idx, loss partial ----
    const int warp = tid >> 5, lane = tid & 31;
    double wsum = 0.0;
    for (int t = warp; t < M_TILE; t += 8) {
        unsigned idx = (unsigned)(minkey[t] & 0xffffffffull);
        const float4* er = (const float4*)(emb + (size_t)idx * HID);
        const float4* zr = (const float4*)(z + (size_t)(tokBase + t) * HID);
        float4* outr = (float4*)(out_zst + (size_t)(tokBase + t) * HID);
        #pragma unroll
        for (int j = lane; j < HID / 4; j += 32) {
            float4 e = er[j];
            float4 v = zr[j];
            float dx = e.x - v.x, dy = e.y - v.y;
            float dz = e.z - v.z, dw = e.w - v.w;
            float4 st;
            st.x = v.x + dx; st.y = v.y + dy;
            st.z = v.z + dz; st.w = v.w + dw;
            outr[j] = st;
            wsum += (double)dx * dx + (double)dy * dy +
                    (double)dz * dz + (double)dw * dw;
        }
        if (lane == 0 && write_extra) out_idx[tokBase + t] = (float)idx;
    }
    #pragma unroll
    for (int o = 16; o; o >>= 1)
        wsum += __shfl_down_sync(0xffffffffu, wsum, o);
    if (lane == 0) atomicAdd(bsum, wsum);
    __syncthreads();
    if (tid == 0) g_part[blockIdx.x] = *bsum;
}

// --- finalize losses ----------------------------------------------------------
__global__ void finalize_kernel(float* __restrict__ out_loss) {
    __shared__ double sd[256];
    int tid = threadIdx.x;
    sd[tid] = g_part[tid];
    __syncthreads();
    for (int s = 128; s; s >>= 1) {
        if (tid < s) sd[tid] += sd[tid + s];
        __syncthreads();
    }
    if (tid == 0) {
        float m = (float)(sd[0] / (double)Z_ST_ELEMS);
        out_loss[0] = m;   // codebook_loss
        out_loss[1] = m;   // commit_loss (identical value in reference)
    }
}

// --- launch ---------------------------------------------------------------------
extern "C" void kernel_launch(void* const* d_in, const int* in_sizes, int n_in,
                              void* d_out, int out_size) {
    const float* z   = (const float*)d_in[0];
    const float* emb = (const float*)d_in[1];
    float* out = (float*)d_out;

    cudaFuncSetAttribute(vq_main, cudaFuncAttributeMaxDynamicSharedMemorySize,
                         SMEM_BYTES);

    int full = (out_size >= FULL_OUT) ? 1 : 0;
    float* out_idx = full ? (out + Z_ST_ELEMS) : nullptr;

    e2_kernel<<<NCODES / 8, 256>>>(emb);
    vq_main<<<NBLOCKS, 256, SMEM_BYTES>>>(z, emb, out, out_idx, full);
    if (full) finalize_kernel<<<1, 256>>>(out + Z_ST_ELEMS + TOKENS);
}

// round 4
// speedup vs baseline: 1.0022x; 1.0022x over previous
#include <cuda_runtime.h>
#include <cstdint>

// ---------------------------------------------------------------------------
// VQ quantization, bit-faithful argmin emulation:
//   dot   : strictly sequential fp32 FMA over ascending k (per output elem)
//   dist  : RN(RN(z2 - 2*dot) + e2)   (reference association)
//   argmin: lowest-index tie break (packed u64 key)
//   z_st  : RN(z + RN(z_q - z))
// ---------------------------------------------------------------------------

#define TOKENS      32768
#define HID         256
#define NCODES      8192
#define M_TILE      128
#define N_TILE      128
#define KC          32
#define NBLOCKS     (TOKENS / M_TILE)     // 256
#define NTILES      (NCODES / N_TILE)     // 64
#define Z_ST_ELEMS  (TOKENS * HID)
#define FULL_OUT    (Z_ST_ELEMS + TOKENS + 2)

typedef unsigned long long ull;

__device__ float  g_e2[NCODES];
__device__ double g_part[NBLOCKS];

// shared memory: As[256][128] f32 (128KB) + Bs[32][128] f32 (16KB) + extras
#define AS_FLOATS (HID * M_TILE)
#define BS_FLOATS (KC * N_TILE)
#define SMEM_BYTES (AS_FLOATS*4 + BS_FLOATS*4 + 128*8 + 128*4 + 8)

__device__ __forceinline__ void ffma2(ull& d, ull a, ull b) {
    asm("fma.rn.f32x2 %0, %1, %2, %0;" : "+l"(d) : "l"(a), "l"(b));
}
__device__ __forceinline__ ull dup2(float s) {
    ull d;
    asm("mov.b64 %0, {%1, %1};" : "=l"(d) : "f"(s));
    return d;
}
__device__ __forceinline__ unsigned fkey(float f) {
    unsigned u = __float_as_uint(f);
    return (u & 0x80000000u) ? ~u : (u | 0x80000000u);
}

// --- ||e||^2 per code, correctly rounded via double ------------------------
__global__ void e2_kernel(const float* __restrict__ emb) {
    int code = blockIdx.x * 8 + (threadIdx.x >> 5);
    int lane = threadIdx.x & 31;
    const float4* r = (const float4*)(emb + (size_t)code * HID);
    double s = 0.0;
    #pragma unroll
    for (int j = lane; j < HID / 4; j += 32) {
        float4 v = r[j];
        s += (double)v.x * v.x + (double)v.y * v.y +
             (double)v.z * v.z + (double)v.w * v.w;
    }
    #pragma unroll
    for (int o = 16; o; o >>= 1)
        s += __shfl_down_sync(0xffffffffu, s, o);
    if (lane == 0) g_e2[code] = (float)s;
}

// --- main kernel ------------------------------------------------------------
__global__ void __launch_bounds__(256, 1)
vq_main(const float* __restrict__ z, const float* __restrict__ emb,
        float* __restrict__ out_zst, float* __restrict__ out_idx,
        int write_extra) {
    extern __shared__ char smem[];
    float* As = (float*)smem;                        // [HID][M_TILE]
    float* Bs = As + AS_FLOATS;                      // [KC][N_TILE]
    ull*    minkey = (ull*)(Bs + BS_FLOATS);         // [128]
    float*  z2s = (float*)(minkey + 128);            // [128]
    double* bsum = (double*)(z2s + 128);

    const int tid = threadIdx.x;
    const int tx = tid & 15;         // n: owns n = tx*8 .. tx*8+7
    const int ty = tid >> 4;         // m: owns m = ty*8 .. ty*8+7
    const int tokBase = blockIdx.x * M_TILE;

    // ---- load A tile (z, full K) into smem, k-major: As[k][m] ----
    {
        const float4* zg4 = (const float4*)(z + (size_t)tokBase * HID);
        #pragma unroll 4
        for (int i = tid; i < M_TILE * (HID / 4); i += 256) {
            int m  = i & 127;
            int kq = i >> 7;           // 0..63
            float4 v = zg4[(size_t)m * (HID / 4) + kq];
            As[(kq * 4 + 0) * M_TILE + m] = v.x;
            As[(kq * 4 + 1) * M_TILE + m] = v.y;
            As[(kq * 4 + 2) * M_TILE + m] = v.z;
            As[(kq * 4 + 3) * M_TILE + m] = v.w;
        }
    }
    __syncthreads();

    // ---- z2 per token (correctly rounded), init minkey ----
    if (tid < 128) {
        double s = 0.0;
        for (int k = 0; k < HID; ++k) {
            float v = As[k * M_TILE + tid];
            s += (double)v * v;
        }
        z2s[tid] = (float)s;
        minkey[tid] = ~0ull;
    }
    if (tid == 0) *bsum = 0.0;
    __syncthreads();

    // B prefetch lane mapping: thread loads code n=ldn, k-quads ldkq+2j
    const int ldn  = tid & 127;
    const int ldkq = tid >> 7;       // 0 or 1
    const float4* eg4 = (const float4*)emb;  // emb[n][k]: idx n*64 + k/4

    for (int nt = 0; nt < NTILES; ++nt) {
        const int nBase = nt * N_TILE;

        ull acc[32];                 // acc[mi*8+nj]: lanes = (m=ty*8+2mi, m+1)
        #pragma unroll
        for (int i = 0; i < 32; ++i) acc[i] = 0ull;

        // prefetch chunk kc=0 of this n-tile
        float4 pf[4];
        #pragma unroll
        for (int j = 0; j < 4; ++j)
            pf[j] = eg4[(size_t)(nBase + ldn) * (HID / 4) + (ldkq + 2 * j)];

        for (int kc = 0; kc < HID / KC; ++kc) {
            __syncthreads();         // Bs consumers of previous chunk done
            // store prefetched chunk: Bs[kk][n]
            #pragma unroll
            for (int j = 0; j < 4; ++j) {
                int kk = (ldkq + 2 * j) * 4;   // local k within chunk
                Bs[(kk + 0) * N_TILE + ldn] = pf[j].x;
                Bs[(kk + 1) * N_TILE + ldn] = pf[j].y;
                Bs[(kk + 2) * N_TILE + ldn] = pf[j].z;
                Bs[(kk + 3) * N_TILE + ldn] = pf[j].w;
            }
            // prefetch next chunk (overlaps FMA section)
            if (kc + 1 < HID / KC) {
                int kqBase = (kc + 1) * (KC / 4);
                #pragma unroll
                for (int j = 0; j < 4; ++j)
                    pf[j] = eg4[(size_t)(nBase + ldn) * (HID / 4) +
                                kqBase + (ldkq + 2 * j)];
            }
            __syncthreads();

            const int kBase = kc * KC;
            #pragma unroll 2
            for (int kk = 0; kk < KC; ++kk) {
                const int k = kBase + kk;
                const ull* a8 = (const ull*)(As + k * M_TILE) + ty * 4;
                ull a0 = a8[0], a1 = a8[1], a2 = a8[2], a3 = a8[3];
                const float4* b4 = (const float4*)(Bs + kk * N_TILE) + tx * 2;
                float4 bA = b4[0], bB = b4[1];
                ull bb0 = dup2(bA.x), bb1 = dup2(bA.y),
                    bb2 = dup2(bA.z), bb3 = dup2(bA.w);
                ull bb4 = dup2(bB.x), bb5 = dup2(bB.y),
                    bb6 = dup2(bB.z), bb7 = dup2(bB.w);
                ffma2(acc[ 0], a0, bb0); ffma2(acc[ 1], a0, bb1);
                ffma2(acc[ 2], a0, bb2); ffma2(acc[ 3], a0, bb3);
                ffma2(acc[ 4], a0, bb4); ffma2(acc[ 5], a0, bb5);
                ffma2(acc[ 6], a0, bb6); ffma2(acc[ 7], a0, bb7);
                ffma2(acc[ 8], a1, bb0); ffma2(acc[ 9], a1, bb1);
                ffma2(acc[10], a1, bb2); ffma2(acc[11], a1, bb3);
                ffma2(acc[12], a1, bb4); ffma2(acc[13], a1, bb5);
                ffma2(acc[14], a1, bb6); ffma2(acc[15], a1, bb7);
                ffma2(acc[16], a2, bb0); ffma2(acc[17], a2, bb1);
                ffma2(acc[18], a2, bb2); ffma2(acc[19], a2, bb3);
                ffma2(acc[20], a2, bb4); ffma2(acc[21], a2, bb5);
                ffma2(acc[22], a2, bb6); ffma2(acc[23], a2, bb7);
                ffma2(acc[24], a3, bb0); ffma2(acc[25], a3, bb1);
                ffma2(acc[26], a3, bb2); ffma2(acc[27], a3, bb3);
                ffma2(acc[28], a3, bb4); ffma2(acc[29], a3, bb5);
                ffma2(acc[30], a3, bb6); ffma2(acc[31], a3, bb7);
            }
        }

        // ---- epilogue: dist + packed argmin (reference rounding chain) ----
        #pragma unroll
        for (int mi = 0; mi < 4; ++mi) {
            int m0 = ty * 8 + 2 * mi;
            float zz0 = z2s[m0], zz1 = z2s[m0 + 1];
            ull best0 = ~0ull, best1 = ~0ull;
            #pragma unroll
            for (int nj = 0; nj < 8; ++nj) {
                int n = nBase + tx * 8 + nj;
                float e2 = __ldg(&g_e2[n]);
                ull A = acc[mi * 8 + nj];
                float dlo = __uint_as_float((unsigned)(A & 0xffffffffull));
                float dhi = __uint_as_float((unsigned)(A >> 32));
                float dist0 = (zz0 - 2.0f * dlo) + e2;
                float dist1 = (zz1 - 2.0f * dhi) + e2;
                ull k0 = ((ull)fkey(dist0) << 32) | (unsigned)n;
                ull k1 = ((ull)fkey(dist1) << 32) | (unsigned)n;
                if (k0 < best0) best0 = k0;
                if (k1 < best1) best1 = k1;
            }
            atomicMin(&minkey[m0], best0);
            atomicMin(&minkey[m0 + 1], best1);
        }
    }
    __syncthreads();

    // ---- phase 2: z_st = z + (z_q - z), idx, loss partial ----
    const int warp = tid >> 5, lane = tid & 31;
    double wsum = 0.0;
    for (int t = warp; t < M_TILE; t += 8) {
        unsigned idx = (unsigned)(minkey[t] & 0xffffffffull);
        const float4* er = (const float4*)(emb + (size_t)idx * HID);
        const float4* zr = (const float4*)(z + (size_t)(tokBase + t) * HID);
        float4* outr = (float4*)(out_zst + (size_t)(tokBase + t) * HID);
        #pragma unroll
        for (int j = lane; j < HID / 4; j += 32) {
            float4 e = er[j];
            float4 v = zr[j];
            float dx = e.x - v.x, dy = e.y - v.y;
            float dz = e.z - v.z, dw = e.w - v.w;
            float4 st;
            st.x = v.x + dx; st.y = v.y + dy;
            st.z = v.z + dz; st.w = v.w + dw;
            outr[j] = st;
            wsum += (double)dx * dx + (double)dy * dy +
                    (double)dz * dz + (double)dw * dw;
        }
        if (lane == 0 && write_extra) out_idx[tokBase + t] = (float)idx;
    }
    #pragma unroll
    for (int o = 16; o; o >>= 1)
        wsum += __shfl_down_sync(0xffffffffu, wsum, o);
    if (lane == 0) atomicAdd(bsum, wsum);
    __syncthreads();
    if (tid == 0) g_part[blockIdx.x] = *bsum;
}

// --- finalize losses ----------------------------------------------------------
__global__ void finalize_kernel(float* __restrict__ out_loss) {
    __shared__ double sd[256];
    int tid = threadIdx.x;
    sd[tid] = g_part[tid];
    __syncthreads();
    for (int s = 128; s; s >>= 1) {
        if (tid < s) sd[tid] += sd[tid + s];
        __syncthreads();
    }
    if (tid == 0) {
        float m = (float)(sd[0] / (double)Z_ST_ELEMS);
        out_loss[0] = m;   // codebook_loss
        out_loss[1] = m;   // commit_loss (identical value in reference)
    }
}

// --- launch ---------------------------------------------------------------------
extern "C" void kernel_launch(void* const* d_in, const int* in_sizes, int n_in,
                              void* d_out, int out_size) {
    const float* z   = (const float*)d_in[0];
    const float* emb = (const float*)d_in[1];
    float* out = (float*)d_out;

    cudaFuncSetAttribute(vq_main, cudaFuncAttributeMaxDynamicSharedMemorySize,
                         SMEM_BYTES);

    int full = (out_size >= FULL_OUT) ? 1 : 0;
    float* out_idx = full ? (out + Z_ST_ELEMS) : nullptr;

    e2_kernel<<<NCODES / 8, 256>>>(emb);
    vq_main<<<NBLOCKS, 256, SMEM_BYTES>>>(z, emb, out, out_idx, full);
    if (full) finalize_kernel<<<1, 256>>>(out + Z_ST_ELEMS + TOKENS);
}

// round 6
// speedup vs baseline: 4.4734x; 4.4635x over previous
#include <cuda_runtime.h>
#include <cuda_bf16.h>
#include <cstdint>

// ============================================================================
// VQ via mma.sync bf16 (baseline PTX, works on sm_103 non-'a' target):
//   approx dist GEMM on tensor cores  ->  candidate filter (DELTA)  ->
//   exact sequential-fp32-FMA-chain recheck (bit-identical to reference).
// ============================================================================

#define TOKENS   32768
#define HID      256
#define NCODES   8192
#define MT       128                  // tokens per CTA
#define NTILE    128                  // codes per B tile
#define NTILES   (NCODES / NTILE)     // 64
#define CAP      32
#define DELTA    0.03f
#define NBLK     (TOKENS / MT)        // 256
#define Z_ST_ELEMS (TOKENS * HID)
#define FULL_OUT   (Z_ST_ELEMS + TOKENS + 2)

#define ROWB     528                  // padded row stride in bytes (512 + 16)

typedef unsigned long long ull;

__device__ __nv_bfloat16 g_zbf[TOKENS * HID];
__device__ __nv_bfloat16 g_ebf[NCODES * HID];
__device__ float  g_e2[NCODES];
__device__ float  g_z2[TOKENS];
__device__ double g_part[NBLK];

// ---- SMEM layout (byte offsets) ----
#define A_OFF   0                       // 128 * 528 = 67584
#define B_OFF   67584                   // 2 * 128 * 528 = 135168
#define CTRL    202752
#define SMINKEY (CTRL + 0)              // 128 u32
#define SCNT    (CTRL + 512)            // 128 u32
#define SCAND   (CTRL + 1024)           // 128*32 u16 = 8192
#define SBSUM   (CTRL + 9216)           // double
#define SMEM_BYTES (CTRL + 9232)

// ---- PTX helpers ----
__device__ __forceinline__ uint32_t smem_u32(const void* p) {
    uint32_t a;
    asm("{ .reg .u64 t; cvta.to.shared.u64 t, %1; cvt.u32.u64 %0, t; }"
        : "=r"(a) : "l"(p));
    return a;
}
__device__ __forceinline__ void cp_async16(uint32_t dst, const void* src) {
    asm volatile("cp.async.cg.shared.global [%0], [%1], 16;\n"
                 :: "r"(dst), "l"(src));
}
#define CP_COMMIT() asm volatile("cp.async.commit_group;" ::: "memory")
#define CP_WAIT0()  asm volatile("cp.async.wait_group 0;" ::: "memory")

#define LDSM4(r, a) \
    asm volatile("ldmatrix.sync.aligned.m8n8.x4.shared.b16 {%0,%1,%2,%3}, [%4];" \
        : "=r"((r)[0]), "=r"((r)[1]), "=r"((r)[2]), "=r"((r)[3]) : "r"(a))

#define MMA16816(d, a, b0, b1) \
    asm volatile("mma.sync.aligned.m16n8k16.row.col.f32.bf16.bf16.f32 " \
        "{%0,%1,%2,%3}, {%4,%5,%6,%7}, {%8,%9}, {%0,%1,%2,%3};" \
        : "+f"((d)[0]), "+f"((d)[1]), "+f"((d)[2]), "+f"((d)[3]) \
        : "r"((a)[0]), "r"((a)[1]), "r"((a)[2]), "r"((a)[3]), "r"(b0), "r"(b1))

__device__ __forceinline__ unsigned fkey(float f) {
    unsigned u = __float_as_uint(f);
    return (u & 0x80000000u) ? ~u : (u | 0x80000000u);
}
__device__ __forceinline__ float unfkey(unsigned k) {
    return (k & 0x80000000u) ? __uint_as_float(k & 0x7fffffffu)
                             : __uint_as_float(~k);
}
// exact sequential fp32 FMA chain over ascending k (reference arithmetic)
__device__ __forceinline__ float exact_dot(const float4* zr, const float4* er) {
    float dot = 0.f;
    #pragma unroll 8
    for (int kk = 0; kk < HID / 4; ++kk) {
        float4 a = zr[kk], b = er[kk];
        dot = fmaf(a.x, b.x, dot);
        dot = fmaf(a.y, b.y, dot);
        dot = fmaf(a.z, b.z, dot);
        dot = fmaf(a.w, b.w, dot);
    }
    return dot;
}

// ---- prep kernels -----------------------------------------------------------
__global__ void prep_e(const float* __restrict__ emb) {
    int code = blockIdx.x * 8 + (threadIdx.x >> 5);
    int lane = threadIdx.x & 31;
    const float* r = emb + (size_t)code * HID;
    double s = 0.0;
    #pragma unroll
    for (int k = lane; k < HID; k += 32) {
        float v = r[k];
        g_ebf[(size_t)code * HID + k] = __float2bfloat16(v);
        s += (double)v * v;
    }
    #pragma unroll
    for (int o = 16; o; o >>= 1) s += __shfl_down_sync(0xffffffffu, s, o);
    if (lane == 0) g_e2[code] = (float)s;
}
__global__ void prep_z(const float* __restrict__ z) {
    int tok = blockIdx.x * 8 + (threadIdx.x >> 5);
    int lane = threadIdx.x & 31;
    const float* r = z + (size_t)tok * HID;
    double s = 0.0;
    #pragma unroll
    for (int k = lane; k < HID; k += 32) {
        float v = r[k];
        g_zbf[(size_t)tok * HID + k] = __float2bfloat16(v);
        s += (double)v * v;
    }
    #pragma unroll
    for (int o = 16; o; o >>= 1) s += __shfl_down_sync(0xffffffffu, s, o);
    if (lane == 0) g_z2[tok] = (float)s;
}

// ---- main kernel --------------------------------------------------------------
__global__ void __launch_bounds__(256, 1)
vq_mma(const float* __restrict__ z, const float* __restrict__ emb,
       float* __restrict__ out_zst, float* __restrict__ out_idx, int write_extra) {
    extern __shared__ char p0[];
    const uint32_t s0 = smem_u32(p0);

    const int tid = threadIdx.x;
    const int wid = tid >> 5, lane = tid & 31;
    const int warpM = wid >> 1, warpN = wid & 1;
    const int g = lane >> 2, tg = lane & 3;
    const int tokBase = blockIdx.x * MT;

    unsigned* mk = (unsigned*)(p0 + SMINKEY);
    unsigned* cc = (unsigned*)(p0 + SCNT);
    unsigned short* cd = (unsigned short*)(p0 + SCAND);

    if (tid < 128) { mk[tid] = 0xFFFFFFFFu; cc[tid] = 0u; }
    if (tid == 0) *(double*)(p0 + SBSUM) = 0.0;

    // ---- prologue: A (whole 128x256) + B tile 0, via cp.async ----
    {
        const char* zsrc = (const char*)g_zbf + (size_t)tokBase * 512;
        #pragma unroll
        for (int i = 0; i < 16; ++i) {
            int u = tid + i * 256, rr = u >> 5, j = u & 31;
            cp_async16(s0 + A_OFF + rr * ROWB + j * 16,
                       zsrc + (size_t)rr * 512 + j * 16);
        }
        const char* bsrc = (const char*)g_ebf;
        #pragma unroll
        for (int i = 0; i < 16; ++i) {
            int u = tid + i * 256, rr = u >> 5, j = u & 31;
            cp_async16(s0 + B_OFF + rr * ROWB + j * 16,
                       bsrc + (size_t)rr * 512 + j * 16);
        }
        CP_COMMIT();
    }

    // per-thread z2 for its 4 token rows
    float z2r[4];
    #pragma unroll
    for (int mf = 0; mf < 2; ++mf)
        #pragma unroll
        for (int h = 0; h < 2; ++h)
            z2r[mf * 2 + h] = g_z2[tokBase + warpM * 32 + mf * 16 + g + h * 8];

    // ldmatrix base addresses
    const uint32_t aB = s0 + A_OFF + (warpM * 32 + (lane & 15)) * ROWB
                        + (lane >> 4) * 16;
    const uint32_t bB0 = s0 + B_OFF + (warpN * 64 + (lane & 15)) * ROWB
                         + (lane >> 4) * 16;

    for (int t = 0; t < NTILES; ++t) {
        CP_WAIT0();
        __syncthreads();
        // issue next B tile into the other buffer
        if (t + 1 < NTILES) {
            const char* bsrc = (const char*)g_ebf + (size_t)(t + 1) * NTILE * 512;
            uint32_t dst = s0 + B_OFF + ((t + 1) & 1) * (NTILE * ROWB);
            #pragma unroll
            for (int i = 0; i < 16; ++i) {
                int u = tid + i * 256, rr = u >> 5, j = u & 31;
                cp_async16(dst + rr * ROWB + j * 16,
                           bsrc + (size_t)rr * 512 + j * 16);
            }
            CP_COMMIT();
        }

        float acc[2][8][4];
        #pragma unroll
        for (int a = 0; a < 2; ++a)
            #pragma unroll
            for (int b = 0; b < 8; ++b)
                #pragma unroll
                for (int c = 0; c < 4; ++c) acc[a][b][c] = 0.f;

        const uint32_t bT = bB0 + (t & 1) * (NTILE * ROWB);

        #pragma unroll 4
        for (int ks = 0; ks < 16; ++ks) {
            uint32_t A0[4], A1[4], Bf0[4], Bf1[4], Bf2[4], Bf3[4];
            LDSM4(A0, aB + ks * 32);
            LDSM4(A1, aB + 16 * ROWB + ks * 32);
            LDSM4(Bf0, bT + ks * 32);
            LDSM4(Bf1, bT + 16 * ROWB + ks * 32);
            LDSM4(Bf2, bT + 32 * ROWB + ks * 32);
            LDSM4(Bf3, bT + 48 * ROWB + ks * 32);
            MMA16816(acc[0][0], A0, Bf0[0], Bf0[2]);
            MMA16816(acc[0][1], A0, Bf0[1], Bf0[3]);
            MMA16816(acc[0][2], A0, Bf1[0], Bf1[2]);
            MMA16816(acc[0][3], A0, Bf1[1], Bf1[3]);
            MMA16816(acc[0][4], A0, Bf2[0], Bf2[2]);
            MMA16816(acc[0][5], A0, Bf2[1], Bf2[3]);
            MMA16816(acc[0][6], A0, Bf3[0], Bf3[2]);
            MMA16816(acc[0][7], A0, Bf3[1], Bf3[3]);
            MMA16816(acc[1][0], A1, Bf0[0], Bf0[2]);
            MMA16816(acc[1][1], A1, Bf0[1], Bf0[3]);
            MMA16816(acc[1][2], A1, Bf1[0], Bf1[2]);
            MMA16816(acc[1][3], A1, Bf1[1], Bf1[3]);
            MMA16816(acc[1][4], A1, Bf2[0], Bf2[2]);
            MMA16816(acc[1][5], A1, Bf2[1], Bf2[3]);
            MMA16816(acc[1][6], A1, Bf3[0], Bf3[2]);
            MMA16816(acc[1][7], A1, Bf3[1], Bf3[3]);
        }

        // ---- epilogue: distances, running min, candidate append ----
        const int nB = t * NTILE + warpN * 64;
        float e2c[16];
        #pragma unroll
        for (int p = 0; p < 4; ++p)
            #pragma unroll
            for (int q = 0; q < 2; ++q)
                #pragma unroll
                for (int e = 0; e < 2; ++e)
                    e2c[p * 4 + q * 2 + e] =
                        __ldg(&g_e2[nB + p * 16 + q * 8 + tg * 2 + e]);

        #pragma unroll
        for (int mf = 0; mf < 2; ++mf)
            #pragma unroll
            for (int h = 0; h < 2; ++h) {
                const int trow = warpM * 32 + mf * 16 + g + h * 8;
                const float z2t = z2r[mf * 2 + h];
                float d[16], lmin = __int_as_float(0x7f800000);
                #pragma unroll
                for (int p = 0; p < 4; ++p)
                    #pragma unroll
                    for (int q = 0; q < 2; ++q)
                        #pragma unroll
                        for (int e = 0; e < 2; ++e) {
                            float dot = acc[mf][p * 2 + q][h * 2 + e];
                            float dist = fmaf(-2.f, dot, z2t)
                                         + e2c[p * 4 + q * 2 + e];
                            d[p * 4 + q * 2 + e] = dist;
                            lmin = fminf(lmin, dist);
                        }
                unsigned cur = mk[trow];
                float thr = fminf(lmin, unfkey(cur)) + DELTA;
                #pragma unroll
                for (int p = 0; p < 4; ++p)
                    #pragma unroll
                    for (int q = 0; q < 2; ++q)
                        #pragma unroll
                        for (int e = 0; e < 2; ++e)
                            if (d[p * 4 + q * 2 + e] <= thr) {
                                unsigned pos = atomicAdd(&cc[trow], 1u);
                                if (pos < CAP)
                                    cd[trow * CAP + pos] = (unsigned short)
                                        (nB + p * 16 + q * 8 + tg * 2 + e);
                            }
                unsigned nk = fkey(lmin);
                if (nk < cur) atomicMin(&mk[trow], nk);
            }
    }
    __syncthreads();

    // ---- exact recheck + z_st + idx + loss (warp per 16 tokens) ----
    float* zrow = (float*)(p0 + B_OFF + wid * 1024);   // B region now free
    double wsum = 0.0;
    for (int t = wid * 16; t < wid * 16 + 16; ++t) {
        const int tok = tokBase + t;
        const float4* zg = (const float4*)(z + (size_t)tok * HID);
        ((float4*)zrow)[lane * 2]     = zg[lane * 2];
        ((float4*)zrow)[lane * 2 + 1] = zg[lane * 2 + 1];
        __syncwarp();

        const unsigned cnt = cc[t];
        const float z2e = g_z2[tok];
        ull key = ~0ull;
        if (cnt <= CAP) {
            if (lane < (int)cnt) {
                int n = cd[t * CAP + lane];
                float dot = exact_dot((const float4*)zrow,
                                      (const float4*)(emb + (size_t)n * HID));
                float dist = (z2e - 2.0f * dot) + __ldg(&g_e2[n]);
                key = ((ull)fkey(dist) << 32) | (unsigned)n;
            }
        } else {
            for (int n = lane; n < NCODES; n += 32) {
                float dot = exact_dot((const float4*)zrow,
                                      (const float4*)(emb + (size_t)n * HID));
                float dist = (z2e - 2.0f * dot) + __ldg(&g_e2[n]);
                ull k = ((ull)fkey(dist) << 32) | (unsigned)n;
                if (k < key) key = k;
            }
        }
        #pragma unroll
        for (int o = 16; o; o >>= 1) {
            ull other = __shfl_down_sync(0xffffffffu, key, o);
            if (other < key) key = other;
        }
        key = __shfl_sync(0xffffffffu, key, 0);
        const unsigned nbest = (unsigned)(key & 0xffffffffull);

        if (lane == 0 && write_extra) out_idx[tok] = (float)nbest;

        const float4* er = (const float4*)(emb + (size_t)nbest * HID);
        float4* outr = (float4*)(out_zst + (size_t)tok * HID);
        #pragma unroll
        for (int q = 0; q < 2; ++q) {
            int j = lane * 2 + q;
            float4 e = er[j], v = ((const float4*)zrow)[j];
            float dx = e.x - v.x, dy = e.y - v.y;
            float dz = e.z - v.z, dw = e.w - v.w;
            float4 stv;
            stv.x = v.x + dx; stv.y = v.y + dy;
            stv.z = v.z + dz; stv.w = v.w + dw;
            outr[j] = stv;
            wsum += (double)dx * dx + (double)dy * dy +
                    (double)dz * dz + (double)dw * dw;
        }
        __syncwarp();
    }
    #pragma unroll
    for (int o = 16; o; o >>= 1)
        wsum += __shfl_down_sync(0xffffffffu, wsum, o);
    if (lane == 0) atomicAdd((double*)(p0 + SBSUM), wsum);
    __syncthreads();
    if (tid == 0) g_part[blockIdx.x] = *(double*)(p0 + SBSUM);
}

// ---- finalize losses ------------------------------------------------------------
__global__ void finalize_kernel(float* __restrict__ out_loss) {
    __shared__ double sd[256];
    int tid = threadIdx.x;
    sd[tid] = g_part[tid];
    __syncthreads();
    for (int s = 128; s; s >>= 1) {
        if (tid < s) sd[tid] += sd[tid + s];
        __syncthreads();
    }
    if (tid == 0) {
        float mloss = (float)(sd[0] / (double)Z_ST_ELEMS);
        out_loss[0] = mloss;
        out_loss[1] = mloss;
    }
}

// ---- launch -----------------------------------------------------------------------
extern "C" void kernel_launch(void* const* d_in, const int* in_sizes, int n_in,
                              void* d_out, int out_size) {
    const float* z   = (const float*)d_in[0];
    const float* emb = (const float*)d_in[1];
    float* out = (float*)d_out;

    cudaFuncSetAttribute(vq_mma, cudaFuncAttributeMaxDynamicSharedMemorySize,
                         SMEM_BYTES);

    int full = (out_size >= FULL_OUT) ? 1 : 0;
    float* out_idx = full ? (out + Z_ST_ELEMS) : nullptr;

    prep_e<<<NCODES / 8, 256>>>(emb);
    prep_z<<<TOKENS / 8, 256>>>(z);
    vq_mma<<<NBLK, 256, SMEM_BYTES>>>(z, emb, out, out_idx, full);
    if (full) finalize_kernel<<<1, 256>>>(out + Z_ST_ELEMS + TOKENS);
}